// round 7
// baseline (speedup 1.0000x reference)
#include <cuda_runtime.h>
#include <math.h>
#include <stdint.h>

#define Bb 8
#define Cc 1536
#define Tt 4096
#define Aa 128
#define K3 (3*Cc)   // 4608

// ---- warp-MMA logits GEMM config ----
#define A_STR 36            // W1 tile [128 a][k] stride (conflict-free frags)
#define B_STR 136           // attn tile [96 k][t] stride (conflict-free frags)
#define NGRP 48             // channel groups of 32
// As + Bs + red + invc
#define SMEM_LOGITS ((128*A_STR + 96*B_STR + 4*128 + 128)*4)

// Scratch (allocation-free rule: __device__ globals)
static __device__ float g_ck1[Bb*32*Cc];   // prefix-sum checkpoints of masked x
static __device__ float g_ck2[Bb*32*Cc];   // prefix-sum checkpoints of masked x^2
static __device__ float g_logits[Bb*Tt];
static __device__ float g_e[Bb*Tt];
static __device__ float g_iZ[Bb*Tt];       // 1 / cumsum(e)  (reciprocal stored!)

__device__ __forceinline__ float f2tf32(float f) {
    uint32_t r;
    asm("cvt.rna.tf32.f32 %0, %1;" : "=r"(r) : "f"(f));
    return __uint_as_float(r);
}

__device__ __forceinline__ void mma_tf32(float* d, const float* a, const float* b)
{
    asm volatile(
        "mma.sync.aligned.m16n8k8.row.col.f32.tf32.tf32.f32 "
        "{%0,%1,%2,%3}, {%4,%5,%6,%7}, {%8,%9}, {%0,%1,%2,%3};"
        : "+f"(d[0]), "+f"(d[1]), "+f"(d[2]), "+f"(d[3])
        : "r"(__float_as_uint(a[0])), "r"(__float_as_uint(a[1])),
          "r"(__float_as_uint(a[2])), "r"(__float_as_uint(a[3])),
          "r"(__float_as_uint(b[0])), "r"(__float_as_uint(b[1])));
}

// Robust lengths read (reference declares int64; JAX w/o x64 emits int32).
__device__ __forceinline__ int load_length(const void* lp, int b)
{
    const int* w = (const int*)lp;
    bool is64 = true;
#pragma unroll
    for (int i = 0; i < 4; i++)
        if (w[2*i + 1] != 0) is64 = false;
    if (is64) return (int)((const long long*)lp)[b];
    return w[b];
}

// Exclusive block scan over 256 per-thread values.
__device__ __forceinline__ float block_excl_scan256(float v, float* ws)
{
    int lane = threadIdx.x & 31;
    int warp = threadIdx.x >> 5;
    float incl = v;
#pragma unroll
    for (int d = 1; d < 32; d <<= 1) {
        float n = __shfl_up_sync(0xffffffffu, incl, d);
        if (lane >= d) incl += n;
    }
    __syncthreads();
    if (lane == 31) ws[warp] = incl;
    __syncthreads();
    if (warp == 0) {
        float wv = (lane < 8) ? ws[lane] : 0.f;
        float wi = wv;
#pragma unroll
        for (int d = 1; d < 8; d <<= 1) {
            float n = __shfl_up_sync(0xffffffffu, wi, d);
            if (lane >= d) wi += n;
        }
        if (lane < 8) ws[lane] = wi - wv;
    }
    __syncthreads();
    return ws[warp] + (incl - v);
}

// ---------------- Kernel 1: prefix checkpoints every 128 t ----------------
__global__ void __launch_bounds__(256) ckpt_kernel(const float* __restrict__ x,
                                                   const void* __restrict__ lengths)
{
    int c = blockIdx.x, b = blockIdx.y;
    size_t roff = ((size_t)b*Cc + c)*(size_t)Tt;
    const float4* row4 = (const float4*)(x + roff);
    int len = load_length(lengths, b);
    __shared__ float ws[8];
    int tid = threadIdx.x;
    int base = tid * 16;

    float c1 = 0.f, c2 = 0.f;
#pragma unroll
    for (int q = 0; q < 4; q++) {
        float4 f = row4[tid*4 + q];
        float vx[4] = {f.x, f.y, f.z, f.w};
#pragma unroll
        for (int j = 0; j < 4; j++) {
            float v = (base + q*4 + j < len) ? vx[j] : 0.f;
            c1 += v; c2 += v*v;
        }
    }
    float o1 = block_excl_scan256(c1, ws);
    float o2 = block_excl_scan256(c2, ws);
    if ((tid & 7) == 0) {
        int m = tid >> 3;                      // tile index 0..31
        g_ck1[((size_t)b*32 + m)*Cc + c] = o1; // prefix over t < 128*m
        g_ck2[((size_t)b*32 + m)*Cc + c] = o2;
    }
}

// ---------------- Kernel 2: fused stats + logits via warp TF32 MMA ----------------
// D[a=128][t=128] = W1[a,k] . attn[k,t]. K grouped: 48 groups x {x, mean, std}.
// invc lives in SMEM (t-only table) to keep thread regs under the (256,2) cap.
__global__ void __launch_bounds__(256, 2) logits_fused_kernel(const float* __restrict__ x,
                                                              const void* __restrict__ lengths,
                                                              const float* __restrict__ W1,
                                                              const float* __restrict__ b1,
                                                              const float* __restrict__ W2,
                                                              const float* __restrict__ b2)
{
    extern __shared__ float sm[];
    float* As   = sm;                       // [128][A_STR]
    float* Bs   = sm + 128*A_STR;           // [96][B_STR]
    float* red  = Bs + 96*B_STR;            // [4][128]
    float* invc = red + 4*128;              // [128] : 1/count per t

    int tid  = threadIdx.x;
    int lane = tid & 31;
    int wid  = tid >> 5;
    int g    = lane >> 2;     // group 0..7
    int tig  = lane & 3;      // thread-in-group
    int wm   = wid >> 1;      // a quadrant 0..3
    int wn   = wid & 1;       // t half 0..1
    int b    = blockIdx.y;
    int m    = blockIdx.x;    // t tile index
    int t0   = m * 128;
    int len  = load_length(lengths, b);

    // Producer mappings
    int pc   = tid >> 3;           // channel row within group (0..31)
    int seg  = tid & 7;            // 16-t segment
    int tb   = t0 + seg*16;        // this thread's first t
    int pa   = tid >> 1;           // W1: a row
    int pkh  = (tid & 1) * 16;     // W1: k half

    // inv counts -> smem (depends only on t; computed once)
    if (tid < 128) {
        int cn = t0 + tid + 1; if (cn > len) cn = len; if (cn < 1) cn = 1;
        invc[tid] = 1.f / (float)cn;
    }

    float acc[2][8][4];
#pragma unroll
    for (int mi = 0; mi < 2; mi++)
#pragma unroll
        for (int ni = 0; ni < 8; ni++)
#pragma unroll
            for (int r = 0; r < 4; r++) acc[mi][ni][r] = 0.f;

    float ast[16];   // staged x tile row segment
    auto stage_x = [&](int cg) {
        const float4* p = (const float4*)(x + ((size_t)b*Cc + cg*32 + pc)*(size_t)Tt + tb);
#pragma unroll
        for (int q = 0; q < 4; q++) ((float4*)ast)[q] = __ldg(p + q);
    };
    stage_x(0);

    float bb1 = 0.f, bb2 = 0.f;   // scan bases (checkpoint + cross-thread exclusive)

    for (int ch = 0; ch < 3*NGRP; ch++) {
        int cg = ch / 3;
        int co = ch - cg*3;

        // W1 staging for this chunk (k0 = co*Cc + cg*32)
        float4 wv[4];
        {
            const float4* wrow = (const float4*)(W1 + (size_t)pa*K3 + co*Cc + cg*32 + pkh);
#pragma unroll
            for (int q = 0; q < 4; q++) wv[q] = __ldg(wrow + q);
        }

        if (co == 0) {
            // per-thread masked sums + 8-lane segmented inclusive scan
            float s1 = 0.f, s2 = 0.f;
#pragma unroll
            for (int j = 0; j < 16; j++) {
                float v = (tb + j < len) ? ast[j] : 0.f;
                s1 += v; s2 += v*v;
            }
            float i1 = s1, i2 = s2;
#pragma unroll
            for (int d = 1; d < 8; d <<= 1) {
                float n1 = __shfl_up_sync(0xffffffffu, i1, d);
                float n2 = __shfl_up_sync(0xffffffffu, i2, d);
                if ((lane & 7) >= d) { i1 += n1; i2 += n2; }
            }
            int cgl = cg*32 + pc;
            bb1 = g_ck1[((size_t)b*32 + m)*Cc + cgl] + (i1 - s1);
            bb2 = g_ck2[((size_t)b*32 + m)*Cc + cgl] + (i2 - s2);
        }

        __syncthreads();   // consumers done with previous As (and Bs at group edge)

        if (co == 0) {
            // emit x / mean / std rows (store-as-you-go)
            float r1 = 0.f, r2 = 0.f;
            float* bx = &Bs[(pc     )*B_STR + seg*16];
            float* bm = &Bs[(32 + pc)*B_STR + seg*16];
            float* bsd= &Bs[(64 + pc)*B_STR + seg*16];
            const float* ivc = &invc[seg*16];
#pragma unroll
            for (int j = 0; j < 16; j++) {
                float rv = ast[j];
                float v  = (tb + j < len) ? rv : 0.f;
                r1 += v; r2 += v*v;
                float ic   = ivc[j];
                float mean = (bb1 + r1) * ic;
                float var  = (bb2 + r2) * ic - mean*mean;
                float sd   = sqrtf(fmaxf(var, 1e-12f));
                bx[j]  = f2tf32(rv);
                bm[j]  = f2tf32(mean);
                bsd[j] = f2tf32(sd);
            }
        }
        // store W1 -> As
#pragma unroll
        for (int q = 0; q < 4; q++) {
            float* d = &As[pa*A_STR + pkh + q*4];
            d[0] = f2tf32(wv[q].x); d[1] = f2tf32(wv[q].y);
            d[2] = f2tf32(wv[q].z); d[3] = f2tf32(wv[q].w);
        }
        __syncthreads();

        if (co == 2 && cg + 1 < NGRP) stage_x(cg + 1);   // prefetch overlaps compute

        int brow0 = co * 32;
#pragma unroll
        for (int ks = 0; ks < 4; ks++) {
            int kb = ks * 8;
            float a_fr[2][4];
#pragma unroll
            for (int mi = 0; mi < 2; mi++) {
                int ar = wm*32 + mi*16;
                a_fr[mi][0] = As[(ar + g    )*A_STR + kb + tig];
                a_fr[mi][1] = As[(ar + 8 + g)*A_STR + kb + tig];
                a_fr[mi][2] = As[(ar + g    )*A_STR + kb + tig + 4];
                a_fr[mi][3] = As[(ar + 8 + g)*A_STR + kb + tig + 4];
            }
            float b_fr[8][2];
#pragma unroll
            for (int ni = 0; ni < 8; ni++) {
                int t = wn*64 + ni*8 + g;
                b_fr[ni][0] = Bs[(brow0 + kb + tig    )*B_STR + t];
                b_fr[ni][1] = Bs[(brow0 + kb + tig + 4)*B_STR + t];
            }
#pragma unroll
            for (int mi = 0; mi < 2; mi++)
#pragma unroll
                for (int ni = 0; ni < 8; ni++)
                    mma_tf32(acc[mi][ni], a_fr[mi], b_fr[ni]);
        }
    }

    // Epilogue: tanh + W2 dot over a, reduce to logits[t]
    float part[16];
#pragma unroll
    for (int i = 0; i < 16; i++) part[i] = 0.f;
#pragma unroll
    for (int mi = 0; mi < 2; mi++) {
        int abase = wm*32 + mi*16;
        float b1a = __ldg(b1 + abase + g),     w2a = __ldg(W2 + abase + g);
        float b1b = __ldg(b1 + abase + 8 + g), w2b = __ldg(W2 + abase + 8 + g);
#pragma unroll
        for (int ni = 0; ni < 8; ni++) {
            part[ni*2+0] += w2a*tanhf(acc[mi][ni][0] + b1a) + w2b*tanhf(acc[mi][ni][2] + b1b);
            part[ni*2+1] += w2a*tanhf(acc[mi][ni][1] + b1a) + w2b*tanhf(acc[mi][ni][3] + b1b);
        }
    }
#pragma unroll
    for (int o = 4; o <= 16; o <<= 1)
#pragma unroll
        for (int i = 0; i < 16; i++)
            part[i] += __shfl_xor_sync(0xffffffffu, part[i], o);
    if (lane < 4) {
#pragma unroll
        for (int ni = 0; ni < 8; ni++) {
            red[wm*128 + wn*64 + ni*8 + lane*2 + 0] = part[ni*2+0];
            red[wm*128 + wn*64 + ni*8 + lane*2 + 1] = part[ni*2+1];
        }
    }
    __syncthreads();
    if (tid < 128) {
        float s = red[tid] + red[128 + tid] + red[256 + tid] + red[384 + tid];
        g_logits[b*Tt + t0 + tid] = s + __ldg(b2);
    }
}

// ---------------- Kernel 3: per-batch max, e = exp(l - max), iZ = 1/cumsum(e) ----------------
__global__ void __launch_bounds__(256) softmax_kernel()
{
    int b = blockIdx.x;
    __shared__ float ls[Tt];
    __shared__ float ws[8];
    __shared__ float red[8];
    int tid = threadIdx.x;
    int lane = tid & 31, warp = tid >> 5;

    float mx = -3.4e38f;
    for (int i = tid; i < Tt; i += 256) {
        float v = g_logits[b*Tt + i];
        ls[i] = v;
        mx = fmaxf(mx, v);
    }
#pragma unroll
    for (int d = 16; d; d >>= 1) mx = fmaxf(mx, __shfl_xor_sync(0xffffffffu, mx, d));
    if (lane == 0) red[warp] = mx;
    __syncthreads();
    if (tid == 0) {
        float m = red[0];
        for (int i = 1; i < 8; i++) m = fmaxf(m, red[i]);
        red[0] = m;
    }
    __syncthreads();
    mx = red[0];

    int base = tid * 16;
    float ev[16], l1[16];
    float c1 = 0.f;
#pragma unroll
    for (int j = 0; j < 16; j++) {
        float e = expf(ls[base + j] - mx);
        ev[j] = e; c1 += e; l1[j] = c1;
    }
    float o1 = block_excl_scan256(c1, ws);
    float4* e4 = (float4*)(g_e  + b*Tt + base);
    float4* z4 = (float4*)(g_iZ + b*Tt + base);
#pragma unroll
    for (int q = 0; q < 4; q++) {
        e4[q] = make_float4(ev[q*4], ev[q*4+1], ev[q*4+2], ev[q*4+3]);
        z4[q] = make_float4(1.f/(o1+l1[q*4]),   1.f/(o1+l1[q*4+1]),
                            1.f/(o1+l1[q*4+2]), 1.f/(o1+l1[q*4+3]));
    }
}

// ---------------- Kernel 4: weighted mean/std pooling + final reduce ----------------
__global__ void __launch_bounds__(256) pool_kernel(const float* __restrict__ x,
                                                   float* __restrict__ out)
{
    int c = blockIdx.x, b = blockIdx.y;
    size_t roff = ((size_t)b*Cc + c)*(size_t)Tt;
    int tid = threadIdx.x;
    __shared__ float ws[8];
    __shared__ float red[8];
    int lane = tid & 31, warp = tid >> 5;

    const float4* x4 = (const float4*)(x + roff);
    const float4* e4 = (const float4*)(g_e  + b*Tt);
    const float4* z4 = (const float4*)(g_iZ + b*Tt);

    float xv[16], ev[16], zv[16];
#pragma unroll
    for (int q = 0; q < 4; q++) {
        float4 f = x4[tid*4 + q]; xv[q*4]=f.x; xv[q*4+1]=f.y; xv[q*4+2]=f.z; xv[q*4+3]=f.w;
        f = e4[tid*4 + q];        ev[q*4]=f.x; ev[q*4+1]=f.y; ev[q*4+2]=f.z; ev[q*4+3]=f.w;
        f = z4[tid*4 + q];        zv[q*4]=f.x; zv[q*4+1]=f.y; zv[q*4+2]=f.z; zv[q*4+3]=f.w;
    }

    float l1[16];
    float c1 = 0.f;
#pragma unroll
    for (int j = 0; j < 16; j++) { c1 += ev[j]*xv[j]; l1[j] = c1; }
    float o1 = block_excl_scan256(c1, ws);

    float sum_wm = 0.f, sum_ws = 0.f;
    float l2[16];
    float c2 = 0.f;
#pragma unroll
    for (int j = 0; j < 16; j++) {
        float wm = (o1 + l1[j]) * zv[j];     // zv holds 1/Z
        sum_wm += wm;
        float d = xv[j] - wm;
        c2 += ev[j]*d*d;
        l2[j] = c2;
    }
    float o2 = block_excl_scan256(c2, ws);
#pragma unroll
    for (int j = 0; j < 16; j++) {
        float wv = (o2 + l2[j]) * zv[j];     // zv holds 1/Z
        sum_ws += sqrtf(fmaxf(wv, 1e-12f));
    }

#pragma unroll
    for (int d = 16; d; d >>= 1) {
        sum_wm += __shfl_xor_sync(0xffffffffu, sum_wm, d);
        sum_ws += __shfl_xor_sync(0xffffffffu, sum_ws, d);
    }
    if (lane == 0) red[warp] = sum_wm;
    __syncthreads();
    if (tid == 0) {
        float tot_m = 0.f;
        for (int i = 0; i < 8; i++) tot_m += red[i];
        red[0] = tot_m;
    }
    __syncthreads();
    float tot_m = red[0];
    __syncthreads();
    if (lane == 0) red[warp] = sum_ws;
    __syncthreads();
    if (tid == 0) {
        float tot_s = 0.f;
        for (int i = 0; i < 8; i++) tot_s += red[i];
        const float fw = (float)(1.0 / (4096.0 + 1e-12));
        out[(size_t)b*(2*Cc) + c]      = tot_m * fw;
        out[(size_t)b*(2*Cc) + Cc + c] = tot_s * fw;
    }
}

extern "C" void kernel_launch(void* const* d_in, const int* in_sizes, int n_in,
                              void* d_out, int out_size)
{
    const float* x       = (const float*)d_in[0];
    const void*  lengths = d_in[1];            // int32 or int64, auto-detected
    const float* W1      = (const float*)d_in[2];
    const float* b1      = (const float*)d_in[3];
    const float* W2      = (const float*)d_in[4];
    const float* b2      = (const float*)d_in[5];
    float* out = (float*)d_out;

    // Idempotent, host-side, not a captured op.
    cudaFuncSetAttribute(logits_fused_kernel,
                         cudaFuncAttributeMaxDynamicSharedMemorySize, SMEM_LOGITS);

    dim3 gs(Cc, Bb);
    ckpt_kernel<<<gs, 256>>>(x, lengths);
    dim3 gl(Tt / 128, Bb);
    logits_fused_kernel<<<gl, 256, SMEM_LOGITS>>>(x, lengths, W1, b1, W2, b2);
    softmax_kernel<<<Bb, 256>>>();
    pool_kernel<<<gs, 256>>>(x, out);
}

// round 8
// speedup vs baseline: 1.1851x; 1.1851x over previous
#include <cuda_runtime.h>
#include <cuda_bf16.h>
#include <math.h>
#include <stdint.h>

#define Bb 8
#define Cc 1536
#define Tt 4096
#define Aa 128
#define K3 (3*Cc)   // 4608

// ---- warp-MMA logits GEMM config ----
#define BKC 32              // K per chunk
#define NCH (K3/BKC)        // 144
#define A_STR 36            // W1 tile [128 a][k] stride (conflict-free frags)
#define B_STR 136           // attn tile [32 k][t] stride (conflict-free frags)

// Scratch (allocation-free rule: __device__ globals)
static __device__ __nv_bfloat162 g_ms[(size_t)Bb*Cc*Tt];  // packed (mean, std)
static __device__ float g_logits[Bb*Tt];
static __device__ float g_e[Bb*Tt];
static __device__ float g_iZ[Bb*Tt];       // 1 / cumsum(e)

__device__ __forceinline__ float f2tf32(float f) {
    uint32_t r;
    asm("cvt.rna.tf32.f32 %0, %1;" : "=r"(r) : "f"(f));
    return __uint_as_float(r);
}

__device__ __forceinline__ void mma_tf32(float* d, const float* a, const float* b)
{
    asm volatile(
        "mma.sync.aligned.m16n8k8.row.col.f32.tf32.tf32.f32 "
        "{%0,%1,%2,%3}, {%4,%5,%6,%7}, {%8,%9}, {%0,%1,%2,%3};"
        : "+f"(d[0]), "+f"(d[1]), "+f"(d[2]), "+f"(d[3])
        : "r"(__float_as_uint(a[0])), "r"(__float_as_uint(a[1])),
          "r"(__float_as_uint(a[2])), "r"(__float_as_uint(a[3])),
          "r"(__float_as_uint(b[0])), "r"(__float_as_uint(b[1])));
}

// Robust lengths read (reference declares int64; JAX w/o x64 emits int32).
__device__ __forceinline__ int load_length(const void* lp, int b)
{
    const int* w = (const int*)lp;
    bool is64 = true;
#pragma unroll
    for (int i = 0; i < 4; i++)
        if (w[2*i + 1] != 0) is64 = false;
    if (is64) return (int)((const long long*)lp)[b];
    return w[b];
}

// Exclusive block scan over 256 per-thread values.
__device__ __forceinline__ float block_excl_scan256(float v, float* ws)
{
    int lane = threadIdx.x & 31;
    int warp = threadIdx.x >> 5;
    float incl = v;
#pragma unroll
    for (int d = 1; d < 32; d <<= 1) {
        float n = __shfl_up_sync(0xffffffffu, incl, d);
        if (lane >= d) incl += n;
    }
    __syncthreads();
    if (lane == 31) ws[warp] = incl;
    __syncthreads();
    if (warp == 0) {
        float wv = (lane < 8) ? ws[lane] : 0.f;
        float wi = wv;
#pragma unroll
        for (int d = 1; d < 8; d <<= 1) {
            float n = __shfl_up_sync(0xffffffffu, wi, d);
            if (lane >= d) wi += n;
        }
        if (lane < 8) ws[lane] = wi - wv;
    }
    __syncthreads();
    return ws[warp] + (incl - v);
}

// ---------------- Kernel 1: causal mean / std (packed bf16x2 output) ----------------
__global__ void __launch_bounds__(256) stats_kernel(const float* __restrict__ x,
                                                    const void* __restrict__ lengths)
{
    int c = blockIdx.x, b = blockIdx.y;
    size_t roff = ((size_t)b*Cc + c)*(size_t)Tt;
    const float4* row4 = (const float4*)(x + roff);
    uint4* ms4 = (uint4*)(g_ms + roff);     // 4 bf16x2 per uint4
    int len = load_length(lengths, b);
    __shared__ float ws[8];
    int tid = threadIdx.x;
    int base = tid * 16;

    float xv[16];
#pragma unroll
    for (int q = 0; q < 4; q++) {
        float4 f = row4[tid*4 + q];
        xv[q*4+0]=f.x; xv[q*4+1]=f.y; xv[q*4+2]=f.z; xv[q*4+3]=f.w;
    }
    float l1[16], l2[16];
    float c1 = 0.f, c2 = 0.f;
#pragma unroll
    for (int j = 0; j < 16; j++) {
        int t = base + j;
        float v = (t < len) ? xv[j] : 0.f;
        c1 += v; c2 += v*v;
        l1[j] = c1; l2[j] = c2;
    }
    float o1 = block_excl_scan256(c1, ws);
    float o2 = block_excl_scan256(c2, ws);

#pragma unroll
    for (int q = 0; q < 4; q++) {
        uint4 pk;
        uint32_t* pw = (uint32_t*)&pk;
#pragma unroll
        for (int j = 0; j < 4; j++) {
            int jj = q*4 + j;
            int t = base + jj;
            int cn = (t + 1 < len) ? (t + 1) : len;
            float cnt = (cn < 1) ? 1.f : (float)cn;
            float m = (o1 + l1[jj]) / cnt;
            float var = (o2 + l2[jj]) / cnt - m*m;
            float sd = sqrtf(fmaxf(var, 1e-12f));
            __nv_bfloat162 h;
            h.x = __float2bfloat16_rn(m);
            h.y = __float2bfloat16_rn(sd);
            pw[j] = *(uint32_t*)&h;
        }
        ms4[tid*4 + q] = pk;
    }
}

// ---------------- Kernel 2: logits via warp-level TF32 MMA (R5 structure) ----------------
// D[a=128][t=128] = W1[a,k] . attn[k,t]; warp grid 4(a) x 2(t), warp tile 32x64.
// attn rows: k<1536 from x (fp32), else from packed bf16x2 g_ms (lo=mean, hi=std).
__global__ void __launch_bounds__(256, 2) logits_mma_kernel(const float* __restrict__ x,
                                                            const float* __restrict__ W1,
                                                            const float* __restrict__ b1,
                                                            const float* __restrict__ W2,
                                                            const float* __restrict__ b2)
{
    __shared__ float As[128 * A_STR];   // W1 tile, [a][k] stride 36  (18432 B)
    __shared__ float Bs[BKC * B_STR];   // attn tile, [k][t] stride 136 (17408 B)
    __shared__ float red[4][128];

    int tid  = threadIdx.x;
    int lane = tid & 31;
    int wid  = tid >> 5;
    int g    = lane >> 2;     // group 0..7
    int tig  = lane & 3;      // thread-in-group
    int wm   = wid >> 1;      // a quadrant 0..3
    int wn   = wid & 1;       // t half 0..1
    int b    = blockIdx.y;
    int t0   = blockIdx.x * 128;

    // Producer mappings
    int pa  = tid >> 1;            // W1: a row
    int pkh = (tid & 1) * 16;      // W1: k half
    int pk  = tid >> 3;            // attn: k row 0..31
    int pt8 = tid & 7;             // attn: 16B lane (covers t = 4*(pt8+8q)..+4)

    float acc[2][8][4];
#pragma unroll
    for (int mi = 0; mi < 2; mi++)
#pragma unroll
        for (int ni = 0; ni < 8; ni++)
#pragma unroll
            for (int r = 0; r < 4; r++) acc[mi][ni][r] = 0.f;

    uint4 ast[4];   // attn staging (prefetch); fp32x4 or bf16x2 x4 per uint4

    // attn source for chunk ch (k0 = ch*32; both x and g_ms cover the same t per uint4)
    auto stage_attn = [&](int ch) {
        int k0 = ch * BKC;
        if (k0 < Cc) {
            const uint4* p = (const uint4*)(x + ((size_t)b*Cc + k0 + pk)*(size_t)Tt + t0);
#pragma unroll
            for (int q = 0; q < 4; q++) ast[q] = __ldg(p + pt8 + q*8);
        } else {
            int crow = (k0 < 2*Cc) ? (k0 - Cc) : (k0 - 2*Cc);
            const uint4* p = (const uint4*)(g_ms + ((size_t)b*Cc + crow + pk)*(size_t)Tt + t0);
#pragma unroll
            for (int q = 0; q < 4; q++) ast[q] = __ldg(p + pt8 + q*8);
        }
    };

    stage_attn(0);

    for (int ch = 0; ch < NCH; ch++) {
        int k0 = ch * BKC;
        // W1 loads (L2-resident after first wave)
        float4 wv[4];
        const float4* wrow = (const float4*)(W1 + (size_t)pa*K3 + k0 + pkh);
#pragma unroll
        for (int q = 0; q < 4; q++) wv[q] = __ldg(wrow + q);

        __syncthreads();   // consumers done with previous tiles

        // store attn staging -> Bs (tf32-rounded); same smem addressing for both paths
        if (k0 < Cc) {
#pragma unroll
            for (int q = 0; q < 4; q++) {
                float4 f = *(float4*)&ast[q];
                float* d = &Bs[pk*B_STR + (pt8 + q*8)*4];
                d[0] = f2tf32(f.x); d[1] = f2tf32(f.y);
                d[2] = f2tf32(f.z); d[3] = f2tf32(f.w);
            }
        } else {
            bool hi = (k0 >= 2*Cc);   // std lives in the high half
#pragma unroll
            for (int q = 0; q < 4; q++) {
                const __nv_bfloat162* h = (const __nv_bfloat162*)&ast[q];
                float* d = &Bs[pk*B_STR + (pt8 + q*8)*4];
#pragma unroll
                for (int j = 0; j < 4; j++) {
                    float v = hi ? __high2float(h[j]) : __low2float(h[j]);
                    d[j] = f2tf32(v);
                }
            }
        }
        // store W1 -> As
#pragma unroll
        for (int q = 0; q < 4; q++) {
            float* d = &As[pa*A_STR + pkh + q*4];
            d[0] = f2tf32(wv[q].x); d[1] = f2tf32(wv[q].y);
            d[2] = f2tf32(wv[q].z); d[3] = f2tf32(wv[q].w);
        }
        __syncthreads();

        if (ch + 1 < NCH) stage_attn(ch + 1);   // prefetch overlaps compute

#pragma unroll
        for (int ks = 0; ks < 4; ks++) {
            int kb = ks * 8;
            float a_fr[2][4];
#pragma unroll
            for (int mi = 0; mi < 2; mi++) {
                int ar = wm*32 + mi*16;
                a_fr[mi][0] = As[(ar + g    )*A_STR + kb + tig];
                a_fr[mi][1] = As[(ar + 8 + g)*A_STR + kb + tig];
                a_fr[mi][2] = As[(ar + g    )*A_STR + kb + tig + 4];
                a_fr[mi][3] = As[(ar + 8 + g)*A_STR + kb + tig + 4];
            }
            float b_fr[8][2];
#pragma unroll
            for (int ni = 0; ni < 8; ni++) {
                int t = wn*64 + ni*8 + g;
                b_fr[ni][0] = Bs[(kb + tig    )*B_STR + t];
                b_fr[ni][1] = Bs[(kb + tig + 4)*B_STR + t];
            }
#pragma unroll
            for (int mi = 0; mi < 2; mi++)
#pragma unroll
                for (int ni = 0; ni < 8; ni++)
                    mma_tf32(acc[mi][ni], a_fr[mi], b_fr[ni]);
        }
    }

    // Epilogue: tanh + W2 dot over a, reduce to logits[t]
    float part[16];
#pragma unroll
    for (int i = 0; i < 16; i++) part[i] = 0.f;
#pragma unroll
    for (int mi = 0; mi < 2; mi++) {
        int abase = wm*32 + mi*16;
        float b1a = __ldg(b1 + abase + g),     w2a = __ldg(W2 + abase + g);
        float b1b = __ldg(b1 + abase + 8 + g), w2b = __ldg(W2 + abase + 8 + g);
#pragma unroll
        for (int ni = 0; ni < 8; ni++) {
            part[ni*2+0] += w2a*tanhf(acc[mi][ni][0] + b1a) + w2b*tanhf(acc[mi][ni][2] + b1b);
            part[ni*2+1] += w2a*tanhf(acc[mi][ni][1] + b1a) + w2b*tanhf(acc[mi][ni][3] + b1b);
        }
    }
#pragma unroll
    for (int o = 4; o <= 16; o <<= 1)
#pragma unroll
        for (int i = 0; i < 16; i++)
            part[i] += __shfl_xor_sync(0xffffffffu, part[i], o);
    if (lane < 4) {
#pragma unroll
        for (int ni = 0; ni < 8; ni++) {
            red[wm][wn*64 + ni*8 + lane*2 + 0] = part[ni*2+0];
            red[wm][wn*64 + ni*8 + lane*2 + 1] = part[ni*2+1];
        }
    }
    __syncthreads();
    if (tid < 128) {
        float s = red[0][tid] + red[1][tid] + red[2][tid] + red[3][tid];
        g_logits[b*Tt + t0 + tid] = s + __ldg(b2);
    }
}

// ---------------- Kernel 3: per-batch max, e = exp(l - max), iZ = 1/cumsum(e) ----------------
__global__ void __launch_bounds__(256) softmax_kernel()
{
    int b = blockIdx.x;
    __shared__ float ls[Tt];
    __shared__ float ws[8];
    __shared__ float red[8];
    int tid = threadIdx.x;
    int lane = tid & 31, warp = tid >> 5;

    float mx = -3.4e38f;
    for (int i = tid; i < Tt; i += 256) {
        float v = g_logits[b*Tt + i];
        ls[i] = v;
        mx = fmaxf(mx, v);
    }
#pragma unroll
    for (int d = 16; d; d >>= 1) mx = fmaxf(mx, __shfl_xor_sync(0xffffffffu, mx, d));
    if (lane == 0) red[warp] = mx;
    __syncthreads();
    if (tid == 0) {
        float m = red[0];
        for (int i = 1; i < 8; i++) m = fmaxf(m, red[i]);
        red[0] = m;
    }
    __syncthreads();
    mx = red[0];

    int base = tid * 16;
    float ev[16], l1[16];
    float c1 = 0.f;
#pragma unroll
    for (int j = 0; j < 16; j++) {
        float e = expf(ls[base + j] - mx);
        ev[j] = e; c1 += e; l1[j] = c1;
    }
    float o1 = block_excl_scan256(c1, ws);
    float4* e4 = (float4*)(g_e  + b*Tt + base);
    float4* z4 = (float4*)(g_iZ + b*Tt + base);
#pragma unroll
    for (int q = 0; q < 4; q++) {
        e4[q] = make_float4(ev[q*4], ev[q*4+1], ev[q*4+2], ev[q*4+3]);
        z4[q] = make_float4(1.f/(o1+l1[q*4]),   1.f/(o1+l1[q*4+1]),
                            1.f/(o1+l1[q*4+2]), 1.f/(o1+l1[q*4+3]));
    }
}

// ---------------- Kernel 4: weighted mean/std pooling + final reduce ----------------
__global__ void __launch_bounds__(256) pool_kernel(const float* __restrict__ x,
                                                   float* __restrict__ out)
{
    int c = blockIdx.x, b = blockIdx.y;
    size_t roff = ((size_t)b*Cc + c)*(size_t)Tt;
    int tid = threadIdx.x;
    __shared__ float ws[8];
    __shared__ float red[8];
    int lane = tid & 31, warp = tid >> 5;

    const float4* x4 = (const float4*)(x + roff);
    const float4* e4 = (const float4*)(g_e  + b*Tt);
    const float4* z4 = (const float4*)(g_iZ + b*Tt);

    float xv[16], ev[16], zv[16];
#pragma unroll
    for (int q = 0; q < 4; q++) {
        float4 f = x4[tid*4 + q]; xv[q*4]=f.x; xv[q*4+1]=f.y; xv[q*4+2]=f.z; xv[q*4+3]=f.w;
        f = e4[tid*4 + q];        ev[q*4]=f.x; ev[q*4+1]=f.y; ev[q*4+2]=f.z; ev[q*4+3]=f.w;
        f = z4[tid*4 + q];        zv[q*4]=f.x; zv[q*4+1]=f.y; zv[q*4+2]=f.z; zv[q*4+3]=f.w;
    }

    float l1[16];
    float c1 = 0.f;
#pragma unroll
    for (int j = 0; j < 16; j++) { c1 += ev[j]*xv[j]; l1[j] = c1; }
    float o1 = block_excl_scan256(c1, ws);

    float sum_wm = 0.f, sum_ws = 0.f;
    float l2[16];
    float c2 = 0.f;
#pragma unroll
    for (int j = 0; j < 16; j++) {
        float wm = (o1 + l1[j]) * zv[j];     // zv holds 1/Z
        sum_wm += wm;
        float d = xv[j] - wm;
        c2 += ev[j]*d*d;
        l2[j] = c2;
    }
    float o2 = block_excl_scan256(c2, ws);
#pragma unroll
    for (int j = 0; j < 16; j++) {
        float wv = (o2 + l2[j]) * zv[j];     // zv holds 1/Z
        sum_ws += sqrtf(fmaxf(wv, 1e-12f));
    }

#pragma unroll
    for (int d = 16; d; d >>= 1) {
        sum_wm += __shfl_xor_sync(0xffffffffu, sum_wm, d);
        sum_ws += __shfl_xor_sync(0xffffffffu, sum_ws, d);
    }
    if (lane == 0) red[warp] = sum_wm;
    __syncthreads();
    if (tid == 0) {
        float tot_m = 0.f;
        for (int i = 0; i < 8; i++) tot_m += red[i];
        red[0] = tot_m;
    }
    __syncthreads();
    float tot_m = red[0];
    __syncthreads();
    if (lane == 0) red[warp] = sum_ws;
    __syncthreads();
    if (tid == 0) {
        float tot_s = 0.f;
        for (int i = 0; i < 8; i++) tot_s += red[i];
        const float fw = (float)(1.0 / (4096.0 + 1e-12));
        out[(size_t)b*(2*Cc) + c]      = tot_m * fw;
        out[(size_t)b*(2*Cc) + Cc + c] = tot_s * fw;
    }
}

extern "C" void kernel_launch(void* const* d_in, const int* in_sizes, int n_in,
                              void* d_out, int out_size)
{
    const float* x       = (const float*)d_in[0];
    const void*  lengths = d_in[1];            // int32 or int64, auto-detected
    const float* W1      = (const float*)d_in[2];
    const float* b1      = (const float*)d_in[3];
    const float* W2      = (const float*)d_in[4];
    const float* b2      = (const float*)d_in[5];
    float* out = (float*)d_out;

    dim3 gs(Cc, Bb);
    stats_kernel<<<gs, 256>>>(x, lengths);
    dim3 gl(Tt / 128, Bb);
    logits_mma_kernel<<<gl, 256>>>(x, W1, b1, W2, b2);
    softmax_kernel<<<Bb, 256>>>();
    pool_kernel<<<gs, 256>>>(x, out);
}

// round 9
// speedup vs baseline: 1.2415x; 1.0476x over previous
#include <cuda_runtime.h>
#include <cuda_bf16.h>
#include <math.h>
#include <stdint.h>

#define Bb 8
#define Cc 1536
#define Tt 4096
#define Aa 128
#define K3 (3*Cc)   // 4608

// ---- warp-MMA logits GEMM config ----
#define BKC 32              // K per chunk
#define NCH (K3/BKC)        // 144
#define A_STR 36            // W1 tile [128 a][k] stride (conflict-free frags)
#define B_STR 136           // attn tile [32 k][t] stride (conflict-free frags)

// Scratch (allocation-free rule: __device__ globals)
static __device__ __nv_bfloat162 g_ms[(size_t)Bb*Cc*Tt];  // packed (mean, std)
static __device__ float g_logits[Bb*Tt];
static __device__ float g_e[Bb*Tt];
static __device__ float g_iZ[Bb*Tt];       // 1 / cumsum(e)

__device__ __forceinline__ float f2tf32(float f) {
    uint32_t r;
    asm("cvt.rna.tf32.f32 %0, %1;" : "=r"(r) : "f"(f));
    return __uint_as_float(r);
}

__device__ __forceinline__ void mma_tf32(float* d, const float* a, const float* b)
{
    asm volatile(
        "mma.sync.aligned.m16n8k8.row.col.f32.tf32.tf32.f32 "
        "{%0,%1,%2,%3}, {%4,%5,%6,%7}, {%8,%9}, {%0,%1,%2,%3};"
        : "+f"(d[0]), "+f"(d[1]), "+f"(d[2]), "+f"(d[3])
        : "r"(__float_as_uint(a[0])), "r"(__float_as_uint(a[1])),
          "r"(__float_as_uint(a[2])), "r"(__float_as_uint(a[3])),
          "r"(__float_as_uint(b[0])), "r"(__float_as_uint(b[1])));
}

// Robust lengths read (reference declares int64; JAX w/o x64 emits int32).
__device__ __forceinline__ int load_length(const void* lp, int b)
{
    const int* w = (const int*)lp;
    bool is64 = true;
#pragma unroll
    for (int i = 0; i < 4; i++)
        if (w[2*i + 1] != 0) is64 = false;
    if (is64) return (int)((const long long*)lp)[b];
    return w[b];
}

// Exclusive block scan, NW warps (NW*32 threads). ws: >= NW floats smem.
template<int NW>
__device__ __forceinline__ float block_excl_scan(float v, float* ws)
{
    int lane = threadIdx.x & 31;
    int warp = threadIdx.x >> 5;
    float incl = v;
#pragma unroll
    for (int d = 1; d < 32; d <<= 1) {
        float n = __shfl_up_sync(0xffffffffu, incl, d);
        if (lane >= d) incl += n;
    }
    __syncthreads();
    if (lane == 31) ws[warp] = incl;
    __syncthreads();
    if (warp == 0) {
        float wv = (lane < NW) ? ws[lane] : 0.f;
        float wi = wv;
#pragma unroll
        for (int d = 1; d < NW; d <<= 1) {
            float n = __shfl_up_sync(0xffffffffu, wi, d);
            if (lane >= d) wi += n;
        }
        if (lane < NW) ws[lane] = wi - wv;
    }
    __syncthreads();
    return ws[warp] + (incl - v);
}

// ---------------- Kernel 1: causal mean / std (512 thr x 8 elems, bf16x2 out) ----------------
__global__ void __launch_bounds__(512, 3) stats_kernel(const float* __restrict__ x,
                                                       const void* __restrict__ lengths)
{
    int c = blockIdx.x, b = blockIdx.y;
    size_t roff = ((size_t)b*Cc + c)*(size_t)Tt;
    const float4* row4 = (const float4*)(x + roff);
    uint4* ms4 = (uint4*)(g_ms + roff);
    int len = load_length(lengths, b);
    __shared__ float ws[16];
    int tid = threadIdx.x;
    int base = tid * 8;

    float xv[8];
#pragma unroll
    for (int q = 0; q < 2; q++) {
        float4 f = row4[tid*2 + q];
        xv[q*4+0]=f.x; xv[q*4+1]=f.y; xv[q*4+2]=f.z; xv[q*4+3]=f.w;
    }
    float c1 = 0.f, c2 = 0.f;
#pragma unroll
    for (int j = 0; j < 8; j++) {
        float v = (base + j < len) ? xv[j] : 0.f;
        c1 += v; c2 += v*v;
    }
    float o1 = block_excl_scan<16>(c1, ws);
    float o2 = block_excl_scan<16>(c2, ws);

    // second pass: recompute running prefixes (bit-identical), emit packed bf16x2
    float r1 = 0.f, r2 = 0.f;
#pragma unroll
    for (int q = 0; q < 2; q++) {
        uint4 pk;
        uint32_t* pw = (uint32_t*)&pk;
#pragma unroll
        for (int j = 0; j < 4; j++) {
            int jj = q*4 + j;
            int t = base + jj;
            float v = (t < len) ? xv[jj] : 0.f;
            r1 += v; r2 += v*v;
            int cn = (t + 1 < len) ? (t + 1) : len;
            float cnt = (cn < 1) ? 1.f : (float)cn;
            float m = (o1 + r1) / cnt;
            float var = (o2 + r2) / cnt - m*m;
            float sd = sqrtf(fmaxf(var, 1e-12f));
            __nv_bfloat162 h;
            h.x = __float2bfloat16_rn(m);
            h.y = __float2bfloat16_rn(sd);
            pw[j] = *(uint32_t*)&h;
        }
        ms4[tid*2 + q] = pk;
    }
}

// ---------------- Kernel 2: logits via warp-level TF32 MMA (R5 structure) ----------------
// D[a=128][t=128] = W1[a,k] . attn[k,t]; warp grid 4(a) x 2(t), warp tile 32x64.
// attn rows: k<1536 from x (fp32), else from packed bf16x2 g_ms (lo=mean, hi=std).
__global__ void __launch_bounds__(256, 2) logits_mma_kernel(const float* __restrict__ x,
                                                            const float* __restrict__ W1,
                                                            const float* __restrict__ b1,
                                                            const float* __restrict__ W2,
                                                            const float* __restrict__ b2)
{
    __shared__ float As[128 * A_STR];   // W1 tile, [a][k] stride 36  (18432 B)
    __shared__ float Bs[BKC * B_STR];   // attn tile, [k][t] stride 136 (17408 B)
    __shared__ float red[4][128];

    int tid  = threadIdx.x;
    int lane = tid & 31;
    int wid  = tid >> 5;
    int g    = lane >> 2;     // group 0..7
    int tig  = lane & 3;      // thread-in-group
    int wm   = wid >> 1;      // a quadrant 0..3
    int wn   = wid & 1;       // t half 0..1
    int b    = blockIdx.y;
    int t0   = blockIdx.x * 128;

    // Producer mappings
    int pa  = tid >> 1;            // W1: a row
    int pkh = (tid & 1) * 16;      // W1: k half
    int pk  = tid >> 3;            // attn: k row 0..31
    int pt8 = tid & 7;             // attn: 16B lane (covers t = 4*(pt8+8q)..+4)

    float acc[2][8][4];
#pragma unroll
    for (int mi = 0; mi < 2; mi++)
#pragma unroll
        for (int ni = 0; ni < 8; ni++)
#pragma unroll
            for (int r = 0; r < 4; r++) acc[mi][ni][r] = 0.f;

    uint4 ast[4];   // attn staging (prefetch); fp32x4 or bf16x2 x4 per uint4

    auto stage_attn = [&](int ch) {
        int k0 = ch * BKC;
        if (k0 < Cc) {
            const uint4* p = (const uint4*)(x + ((size_t)b*Cc + k0 + pk)*(size_t)Tt + t0);
#pragma unroll
            for (int q = 0; q < 4; q++) ast[q] = __ldg(p + pt8 + q*8);
        } else {
            int crow = (k0 < 2*Cc) ? (k0 - Cc) : (k0 - 2*Cc);
            const uint4* p = (const uint4*)(g_ms + ((size_t)b*Cc + crow + pk)*(size_t)Tt + t0);
#pragma unroll
            for (int q = 0; q < 4; q++) ast[q] = __ldg(p + pt8 + q*8);
        }
    };

    stage_attn(0);

    for (int ch = 0; ch < NCH; ch++) {
        int k0 = ch * BKC;
        float4 wv[4];
        const float4* wrow = (const float4*)(W1 + (size_t)pa*K3 + k0 + pkh);
#pragma unroll
        for (int q = 0; q < 4; q++) wv[q] = __ldg(wrow + q);

        __syncthreads();   // consumers done with previous tiles

        if (k0 < Cc) {
#pragma unroll
            for (int q = 0; q < 4; q++) {
                float4 f = *(float4*)&ast[q];
                float* d = &Bs[pk*B_STR + (pt8 + q*8)*4];
                d[0] = f2tf32(f.x); d[1] = f2tf32(f.y);
                d[2] = f2tf32(f.z); d[3] = f2tf32(f.w);
            }
        } else {
            bool hi = (k0 >= 2*Cc);   // std lives in the high half
#pragma unroll
            for (int q = 0; q < 4; q++) {
                const __nv_bfloat162* h = (const __nv_bfloat162*)&ast[q];
                float* d = &Bs[pk*B_STR + (pt8 + q*8)*4];
#pragma unroll
                for (int j = 0; j < 4; j++) {
                    float v = hi ? __high2float(h[j]) : __low2float(h[j]);
                    d[j] = f2tf32(v);
                }
            }
        }
#pragma unroll
        for (int q = 0; q < 4; q++) {
            float* d = &As[pa*A_STR + pkh + q*4];
            d[0] = f2tf32(wv[q].x); d[1] = f2tf32(wv[q].y);
            d[2] = f2tf32(wv[q].z); d[3] = f2tf32(wv[q].w);
        }
        __syncthreads();

        if (ch + 1 < NCH) stage_attn(ch + 1);   // prefetch overlaps compute

#pragma unroll
        for (int ks = 0; ks < 4; ks++) {
            int kb = ks * 8;
            float a_fr[2][4];
#pragma unroll
            for (int mi = 0; mi < 2; mi++) {
                int ar = wm*32 + mi*16;
                a_fr[mi][0] = As[(ar + g    )*A_STR + kb + tig];
                a_fr[mi][1] = As[(ar + 8 + g)*A_STR + kb + tig];
                a_fr[mi][2] = As[(ar + g    )*A_STR + kb + tig + 4];
                a_fr[mi][3] = As[(ar + 8 + g)*A_STR + kb + tig + 4];
            }
            float b_fr[8][2];
#pragma unroll
            for (int ni = 0; ni < 8; ni++) {
                int t = wn*64 + ni*8 + g;
                b_fr[ni][0] = Bs[(kb + tig    )*B_STR + t];
                b_fr[ni][1] = Bs[(kb + tig + 4)*B_STR + t];
            }
#pragma unroll
            for (int mi = 0; mi < 2; mi++)
#pragma unroll
                for (int ni = 0; ni < 8; ni++)
                    mma_tf32(acc[mi][ni], a_fr[mi], b_fr[ni]);
        }
    }

    // Epilogue: tanh + W2 dot over a, reduce to logits[t]
    float part[16];
#pragma unroll
    for (int i = 0; i < 16; i++) part[i] = 0.f;
#pragma unroll
    for (int mi = 0; mi < 2; mi++) {
        int abase = wm*32 + mi*16;
        float b1a = __ldg(b1 + abase + g),     w2a = __ldg(W2 + abase + g);
        float b1b = __ldg(b1 + abase + 8 + g), w2b = __ldg(W2 + abase + 8 + g);
#pragma unroll
        for (int ni = 0; ni < 8; ni++) {
            part[ni*2+0] += w2a*tanhf(acc[mi][ni][0] + b1a) + w2b*tanhf(acc[mi][ni][2] + b1b);
            part[ni*2+1] += w2a*tanhf(acc[mi][ni][1] + b1a) + w2b*tanhf(acc[mi][ni][3] + b1b);
        }
    }
#pragma unroll
    for (int o = 4; o <= 16; o <<= 1)
#pragma unroll
        for (int i = 0; i < 16; i++)
            part[i] += __shfl_xor_sync(0xffffffffu, part[i], o);
    if (lane < 4) {
#pragma unroll
        for (int ni = 0; ni < 8; ni++) {
            red[wm][wn*64 + ni*8 + lane*2 + 0] = part[ni*2+0];
            red[wm][wn*64 + ni*8 + lane*2 + 1] = part[ni*2+1];
        }
    }
    __syncthreads();
    if (tid < 128) {
        float s = red[0][tid] + red[1][tid] + red[2][tid] + red[3][tid];
        g_logits[b*Tt + t0 + tid] = s + __ldg(b2);
    }
}

// ---------------- Kernel 3: per-batch max, e = exp(l - max), iZ = 1/cumsum(e) ----------------
__global__ void __launch_bounds__(256) softmax_kernel()
{
    int b = blockIdx.x;
    __shared__ float ls[Tt];
    __shared__ float ws[8];
    __shared__ float red[8];
    int tid = threadIdx.x;
    int lane = tid & 31, warp = tid >> 5;

    float mx = -3.4e38f;
    for (int i = tid; i < Tt; i += 256) {
        float v = g_logits[b*Tt + i];
        ls[i] = v;
        mx = fmaxf(mx, v);
    }
#pragma unroll
    for (int d = 16; d; d >>= 1) mx = fmaxf(mx, __shfl_xor_sync(0xffffffffu, mx, d));
    if (lane == 0) red[warp] = mx;
    __syncthreads();
    if (tid == 0) {
        float m = red[0];
        for (int i = 1; i < 8; i++) m = fmaxf(m, red[i]);
        red[0] = m;
    }
    __syncthreads();
    mx = red[0];

    int base = tid * 16;
    float ev[16], l1[16];
    float c1 = 0.f;
#pragma unroll
    for (int j = 0; j < 16; j++) {
        float e = expf(ls[base + j] - mx);
        ev[j] = e; c1 += e; l1[j] = c1;
    }
    float o1 = block_excl_scan<8>(c1, ws);
    float4* e4 = (float4*)(g_e  + b*Tt + base);
    float4* z4 = (float4*)(g_iZ + b*Tt + base);
#pragma unroll
    for (int q = 0; q < 4; q++) {
        e4[q] = make_float4(ev[q*4], ev[q*4+1], ev[q*4+2], ev[q*4+3]);
        z4[q] = make_float4(1.f/(o1+l1[q*4]),   1.f/(o1+l1[q*4+1]),
                            1.f/(o1+l1[q*4+2]), 1.f/(o1+l1[q*4+3]));
    }
}

// ---------------- Kernel 4: weighted pooling (512 thr x 8 elems) ----------------
__global__ void __launch_bounds__(512, 3) pool_kernel(const float* __restrict__ x,
                                                      float* __restrict__ out)
{
    int c = blockIdx.x, b = blockIdx.y;
    size_t roff = ((size_t)b*Cc + c)*(size_t)Tt;
    int tid = threadIdx.x;
    __shared__ float ws[16];
    __shared__ float red[16];
    int lane = tid & 31, warp = tid >> 5;

    const float4* x4 = (const float4*)(x + roff);
    const float4* e4 = (const float4*)(g_e  + b*Tt);
    const float4* z4 = (const float4*)(g_iZ + b*Tt);

    float xv[8], ev[8], zv[8];
#pragma unroll
    for (int q = 0; q < 2; q++) {
        float4 f = x4[tid*2 + q]; xv[q*4]=f.x; xv[q*4+1]=f.y; xv[q*4+2]=f.z; xv[q*4+3]=f.w;
        f = e4[tid*2 + q];        ev[q*4]=f.x; ev[q*4+1]=f.y; ev[q*4+2]=f.z; ev[q*4+3]=f.w;
        f = z4[tid*2 + q];        zv[q*4]=f.x; zv[q*4+1]=f.y; zv[q*4+2]=f.z; zv[q*4+3]=f.w;
    }

    float c1 = 0.f;
#pragma unroll
    for (int j = 0; j < 8; j++) c1 += ev[j]*xv[j];
    float o1 = block_excl_scan<16>(c1, ws);

    // pass B: weighted mean + c2 (recompute running prefix)
    float sum_wm = 0.f, c2 = 0.f;
    {
        float r1 = 0.f;
#pragma unroll
        for (int j = 0; j < 8; j++) {
            r1 += ev[j]*xv[j];
            float wm = (o1 + r1) * zv[j];     // zv holds 1/Z
            sum_wm += wm;
            float d = xv[j] - wm;
            c2 += ev[j]*d*d;
        }
    }
    float o2 = block_excl_scan<16>(c2, ws);

    // pass C: weighted std (recompute both running prefixes, bit-identical)
    float sum_ws = 0.f;
    {
        float r1 = 0.f, r2 = 0.f;
#pragma unroll
        for (int j = 0; j < 8; j++) {
            r1 += ev[j]*xv[j];
            float wm = (o1 + r1) * zv[j];
            float d = xv[j] - wm;
            r2 += ev[j]*d*d;
            float wv = (o2 + r2) * zv[j];
            sum_ws += sqrtf(fmaxf(wv, 1e-12f));
        }
    }

#pragma unroll
    for (int d = 16; d; d >>= 1) {
        sum_wm += __shfl_xor_sync(0xffffffffu, sum_wm, d);
        sum_ws += __shfl_xor_sync(0xffffffffu, sum_ws, d);
    }
    if (lane == 0) red[warp] = sum_wm;
    __syncthreads();
    if (tid == 0) {
        float tot_m = 0.f;
        for (int i = 0; i < 16; i++) tot_m += red[i];
        red[0] = tot_m;
    }
    __syncthreads();
    float tot_m = red[0];
    __syncthreads();
    if (lane == 0) red[warp] = sum_ws;
    __syncthreads();
    if (tid == 0) {
        float tot_s = 0.f;
        for (int i = 0; i < 16; i++) tot_s += red[i];
        const float fw = (float)(1.0 / (4096.0 + 1e-12));
        out[(size_t)b*(2*Cc) + c]      = tot_m * fw;
        out[(size_t)b*(2*Cc) + Cc + c] = tot_s * fw;
    }
}

extern "C" void kernel_launch(void* const* d_in, const int* in_sizes, int n_in,
                              void* d_out, int out_size)
{
    const float* x       = (const float*)d_in[0];
    const void*  lengths = d_in[1];            // int32 or int64, auto-detected
    const float* W1      = (const float*)d_in[2];
    const float* b1      = (const float*)d_in[3];
    const float* W2      = (const float*)d_in[4];
    const float* b2      = (const float*)d_in[5];
    float* out = (float*)d_out;

    dim3 gs(Cc, Bb);
    stats_kernel<<<gs, 512>>>(x, lengths);
    dim3 gl(Tt / 128, Bb);
    logits_mma_kernel<<<gl, 256>>>(x, W1, b1, W2, b2);
    softmax_kernel<<<Bb, 256>>>();
    pool_kernel<<<gs, 512>>>(x, out);
}